// round 16
// baseline (speedup 1.0000x reference)
#include <cuda_runtime.h>
#include <cuda_fp16.h>
#include <math.h>
#include <stdint.h>

#define BB 16
#define SS 512
#define HH 1024
#define EE 256
#define VV 50257

// ---------------- device scratch (no allocations allowed) ----------------
__device__ float g_dec_proj[BB * HH];
__device__ float g_score[BB * SS];
__device__ float g_gin[BB * (HH + EE)];
__device__ float g_gi[BB * 3 * HH];         // GRU pre-activations (r|z|n)
__device__ float g_h[BB * HH];
__device__ __half g_enc_hi[SS * BB * HH];   // 16 MB
__device__ __half g_w2_hi[HH * HH];         // 2 MB

__device__ __forceinline__ uint32_t smem_u32(const void* p) {
    uint32_t a;
    asm("{ .reg .u64 t; cvta.to.shared.u64 t, %1; cvt.u32.u64 %0, t; }" : "=r"(a) : "l"(p));
    return a;
}
__device__ __forceinline__ float warp_sum(float v) {
#pragma unroll
    for (int o = 16; o; o >>= 1) v += __shfl_xor_sync(0xffffffffu, v, o);
    return v;
}
__device__ __forceinline__ float warp_max(float v) {
#pragma unroll
    for (int o = 16; o; o >>= 1) v = fmaxf(v, __shfl_xor_sync(0xffffffffu, v, o));
    return v;
}

#define LDSM4(r0, r1, r2, r3, addr) \
    asm volatile("ldmatrix.sync.aligned.m8n8.x4.shared.b16 {%0,%1,%2,%3}, [%4];" \
                 : "=r"(r0), "=r"(r1), "=r"(r2), "=r"(r3) : "r"(addr))

#define MMA16816(cc, a0, a1, a2, a3, b0, b1) \
    asm volatile("mma.sync.aligned.m16n8k16.row.col.f32.f16.f16.f32 " \
                 "{%0,%1,%2,%3}, {%4,%5,%6,%7}, {%8,%9}, {%0,%1,%2,%3};" \
                 : "+f"((cc)[0]), "+f"((cc)[1]), "+f"((cc)[2]), "+f"((cc)[3]) \
                 : "r"(a0), "r"(a1), "r"(a2), "r"(a3), "r"(b0), "r"(b1))

#define CP16(dst, src) \
    asm volatile("cp.async.cg.shared.global [%0], [%1], 16;" :: "r"(dst), "l"(src))

// ---------------- K0: fused prep — cvt (0..1183) + dec_proj/zeroing (1184..1695) ----------------
#define CVT_BLKS 1184
__global__ __launch_bounds__(256) void k_prep(const float* __restrict__ enc,
                                              const float* __restrict__ w2,
                                              __half* __restrict__ ehi,
                                              __half* __restrict__ whi,
                                              const float* __restrict__ dec_hs,
                                              const float* __restrict__ w1_W,
                                              const float* __restrict__ w1_b,
                                              int n4e, int n4w) {
    if (blockIdx.x < CVT_BLKS) {
        const int stride = CVT_BLKS * 256;
        const int total = n4e + n4w;
        for (int i = blockIdx.x * 256 + threadIdx.x; i < total; i += stride) {
            if (i < n4e) {
                float4 v = ((const float4*)enc)[i];
                __half2* hp = (__half2*)ehi;
                hp[i * 2]     = __half2(__float2half_rn(v.x), __float2half_rn(v.y));
                hp[i * 2 + 1] = __half2(__float2half_rn(v.z), __float2half_rn(v.w));
            } else {
                int j = i - n4e;
                float4 v = ((const float4*)w2)[j];
                __half2* hp = (__half2*)whi;
                hp[j * 2]     = __half2(__float2half_rn(v.x), __float2half_rn(v.y));
                hp[j * 2 + 1] = __half2(__float2half_rn(v.z), __float2half_rn(v.w));
            }
        }
        return;
    }
    const int blk = blockIdx.x - CVT_BLKS;   // 0..511
    if (threadIdx.x < 16) g_score[blk * 16 + threadIdx.x] = 0.f;
    if (threadIdx.x >= 32 && threadIdx.x < 72)                 // 512*40 = BB*(HH+EE)
        g_gin[blk * 40 + (threadIdx.x - 32)] = 0.f;
    if (threadIdx.x >= 72 && threadIdx.x < 168)                // 512*96 = BB*3*HH
        g_gi[blk * 96 + (threadIdx.x - 72)] = 0.f;

    const int gw = blk * 8 + (threadIdx.x >> 5);   // 0..4095
    const int lane = threadIdx.x & 31;
    const int j = gw >> 2, b0 = (gw & 3) * 4;
    float acc[4] = {0.f, 0.f, 0.f, 0.f};
#pragma unroll
    for (int it = 0; it < 8; it++) {
        const int k = it * 128 + lane * 4;
        float4 w4 = *(const float4*)(w1_W + (size_t)j * HH + k);
#pragma unroll
        for (int b = 0; b < 4; b++) {
            float4 a4 = *(const float4*)(dec_hs + (b0 + b) * HH + k);
            acc[b] += w4.x * a4.x + w4.y * a4.y + w4.z * a4.z + w4.w * a4.w;
        }
    }
#pragma unroll
    for (int b = 0; b < 4; b++) {
        float s = warp_sum(acc[b]);
        if (lane == 0) g_dec_proj[(b0 + b) * HH + j] = s + w1_b[j];
    }
}

// ---------------- K1: fp16 HMMA GEMM + fused score epilogue (R15, unchanged) ----------------
#define MA_A  0u
#define MA_B  10240u
#define STG   20480u
#define GSMEM (4 * 20480)

__global__ void __launch_bounds__(512, 2) k_gemm_score(const float* __restrict__ w2_b,
                                                       const float* __restrict__ va_W) {
    extern __shared__ char dynsmem[];
    const uint32_t sb = smem_u32(dynsmem);

    const int tid = threadIdx.x, wid = tid >> 5, lane = tid & 31;
    const int m0 = blockIdx.y * 128, n0 = blockIdx.x * 128;
    const int wm = wid >> 2, wn = wid & 3;   // warp grid 4M x 4N

    float c[2][4][4];
#pragma unroll
    for (int i = 0; i < 2; i++)
#pragma unroll
        for (int j = 0; j < 4; j++)
#pragma unroll
            for (int e = 0; e < 4; e++) c[i][j][e] = 0.f;

    const int srow = tid >> 2, sq = tid & 3;
    const size_t gA = (size_t)(m0 + srow) * HH + sq * 8;
    const size_t gB = (size_t)(n0 + srow) * HH + sq * 8;
    const uint32_t drow = (uint32_t)(srow * 80 + sq * 16);

#define PREFETCH(st, k0) do {                                               \
        uint32_t db = sb + (uint32_t)(st) * STG + drow;                     \
        CP16(db + MA_A, g_enc_hi + gA + (k0));                              \
        CP16(db + MA_B, g_w2_hi + gB + (k0));                               \
        asm volatile("cp.async.commit_group;" ::: "memory");                \
    } while (0)

    PREFETCH(0, 0);
    PREFETCH(1, 32);
    PREFETCH(2, 64);

    for (int ch = 0; ch < 32; ch++) {
        if (ch <= 29)      asm volatile("cp.async.wait_group 2;" ::: "memory");
        else if (ch == 30) asm volatile("cp.async.wait_group 1;" ::: "memory");
        else               asm volatile("cp.async.wait_group 0;" ::: "memory");
        __syncthreads();
        if (ch + 3 < 32) PREFETCH((ch + 3) & 3, (ch + 3) * 32);

        const uint32_t base = sb + (uint32_t)(ch & 3) * STG;
        const uint32_t aS = base + MA_A, bS = base + MA_B;

#pragma unroll
        for (int kk = 0; kk < 2; kk++) {
            const int lcol = kk * 16 + (lane >> 4) * 8;
            uint32_t am[2][4];
#pragma unroll
            for (int mi = 0; mi < 2; mi++) {
                int m = wm * 32 + mi * 16 + (lane & 15);
                uint32_t off = (uint32_t)(m * 80 + lcol * 2);
                LDSM4(am[mi][0], am[mi][1], am[mi][2], am[mi][3], aS + off);
            }
            uint32_t bhf[4][2];
#pragma unroll
            for (int g = 0; g < 2; g++) {
                int n = wn * 32 + g * 16 + (lane & 15);
                uint32_t off = (uint32_t)(n * 80 + lcol * 2);
                uint32_t r0, r1, r2, r3;
                LDSM4(r0, r1, r2, r3, bS + off);
                bhf[2 * g][0] = r0; bhf[2 * g + 1][0] = r1;
                bhf[2 * g][1] = r2; bhf[2 * g + 1][1] = r3;
            }
#pragma unroll
            for (int mi = 0; mi < 2; mi++)
#pragma unroll
                for (int ni = 0; ni < 4; ni++)
                    MMA16816(c[mi][ni], am[mi][0], am[mi][1], am[mi][2], am[mi][3],
                             bhf[ni][0], bhf[ni][1]);
        }
    }

    const int lq = lane >> 2, lr = lane & 3;
#pragma unroll
    for (int mi = 0; mi < 2; mi++) {
#pragma unroll
        for (int h = 0; h < 2; h++) {
            int r = m0 + wm * 32 + mi * 16 + lq + 8 * h;   // r = s*16 + b
            int b = r & 15, s = r >> 4;
            const float* dec = g_dec_proj + b * HH;
            float acc = 0.f;
#pragma unroll
            for (int ni = 0; ni < 4; ni++) {
#pragma unroll
                for (int e = 0; e < 2; e++) {
                    int col = n0 + wn * 32 + ni * 8 + 2 * lr + e;
                    float v = c[mi][ni][2 * h + e] + dec[col] + w2_b[col];
                    acc += va_W[col] * tanhf(v);
                }
            }
            acc += __shfl_xor_sync(0xffffffffu, acc, 1);
            acc += __shfl_xor_sync(0xffffffffu, acc, 2);
            if (lr == 0) atomicAdd(&g_score[b * SS + s], acc);
        }
    }
}

// ---------------- K2: fused softmax + context(fp16 enc, s-split) + gin ----------------
__global__ __launch_bounds__(512) void k_smax_ctx(const int* __restrict__ x,
                                                  const float* __restrict__ emb,
                                                  float* __restrict__ attn) {
    __shared__ float a[SS];
    __shared__ float red[16];
    __shared__ float bcast;
    const int b = blockIdx.x, tid = threadIdx.x;

    float s0 = g_score[b * SS + tid];
    float m = warp_max(s0);
    if ((tid & 31) == 0) red[tid >> 5] = m;
    __syncthreads();
    if (tid == 0) {
        float mm = red[0];
#pragma unroll
        for (int i = 1; i < 16; i++) mm = fmaxf(mm, red[i]);
        bcast = mm;
    }
    __syncthreads();
    float e0 = expf(s0 - bcast);
    float ws = warp_sum(e0);
    __syncthreads();
    if ((tid & 31) == 0) red[tid >> 5] = ws;
    __syncthreads();
    if (tid == 0) {
        float sum = 0.f;
#pragma unroll
        for (int i = 0; i < 16; i++) sum += red[i];
        bcast = sum;
    }
    __syncthreads();
    a[tid] = e0 / bcast;
    __syncthreads();

    if (blockIdx.y == 8) {
        attn[b * SS + tid] = a[tid];
        if (tid < EE) g_gin[b * (HH + EE) + HH + tid] = emb[(size_t)x[b] * EE + tid];
        return;
    }

    const int sbase = blockIdx.y * 64;
    const __half2* ep = ((const __half2*)g_enc_hi)
                      + ((size_t)sbase * BB + b) * (HH / 2) + tid;
    float accx = 0.f, accy = 0.f;
#pragma unroll 8
    for (int s = 0; s < 64; s++) {
        float w = a[sbase + s];
        float2 v = __half22float2(ep[(size_t)s * BB * (HH / 2)]);
        accx += w * v.x;
        accy += w * v.y;
    }
    atomicAdd(&g_gin[b * (HH + EE) + 2 * tid],     accx);
    atomicAdd(&g_gin[b * (HH + EE) + 2 * tid + 1], accy);
}

// ---------------- K3: GRU input GEMM via HMMA — gi[16x3072] = gin[16x1280] @ W_ih^T ----------------
// grid (24, 4): x = 128-row tile of 3072, y = K-chunk of 320. Partials atomicAdd into g_gi.
#define KK  (HH + EE)    // 1280
#define GPAD 1304        // padded halves: row stride 2608B, /16 = 163 ≡ 3 (mod 8) — conflict-free
__global__ __launch_bounds__(256) void k_gin_mma(const float* __restrict__ W_ih) {
    __shared__ __half hsm[16][GPAD];
    const int tid = threadIdx.x, wid = tid >> 5, lane = tid & 31;

    // load gin (16 x 1280 fp32) -> fp16 smem
    for (int i = tid; i < 16 * (KK / 2); i += 256) {
        int r = i / (KK / 2), cc = (i % (KK / 2)) * 2;
        float2 v = *(const float2*)(g_gin + r * KK + cc);
        *(__half2*)&hsm[r][cc] = __floats2half2_rn(v.x, v.y);
    }
    __syncthreads();

    const int v0 = blockIdx.x * 128 + wid * 16;       // < 3072 always
    const int kbase = blockIdx.y * 320;
    const int vr0 = v0 + (lane >> 2);
    const int vr1 = v0 + 8 + (lane >> 2);
    const float* wp0 = W_ih + (size_t)vr0 * KK + kbase + 2 * (lane & 3);
    const float* wp1 = W_ih + (size_t)vr1 * KK + kbase + 2 * (lane & 3);

    const uint32_t abase = smem_u32(&hsm[0][0])
                         + (uint32_t)((lane & 15) * (GPAD * 2) + (lane >> 4) * 16
                                      + kbase * 2);

    float c0[4] = {0.f, 0.f, 0.f, 0.f};
    float c1[4] = {0.f, 0.f, 0.f, 0.f};

#pragma unroll 4
    for (int ks = 0; ks < 20; ks++) {
        const int k0 = ks * 16;
        uint32_t a0, a1, a2, a3;
        LDSM4(a0, a1, a2, a3, abase + (uint32_t)(k0 * 2));
        float2 x0 = *(const float2*)(wp0 + k0);
        float2 x1 = *(const float2*)(wp0 + k0 + 8);
        float2 y0 = *(const float2*)(wp1 + k0);
        float2 y1 = *(const float2*)(wp1 + k0 + 8);
        uint32_t r00, r01, r10, r11;
        {
            __half2 t0 = __floats2half2_rn(x0.x, x0.y);
            __half2 t1 = __floats2half2_rn(x1.x, x1.y);
            __half2 t2 = __floats2half2_rn(y0.x, y0.y);
            __half2 t3 = __floats2half2_rn(y1.x, y1.y);
            r00 = *(uint32_t*)&t0; r01 = *(uint32_t*)&t1;
            r10 = *(uint32_t*)&t2; r11 = *(uint32_t*)&t3;
        }
        MMA16816(c0, a0, a1, a2, a3, r00, r01);
        MMA16816(c1, a0, a1, a2, a3, r10, r11);
    }

    const int bq = lane >> 2, vn = 2 * (lane & 3);
#pragma unroll
    for (int t = 0; t < 2; t++) {
        const float* cr = t ? c1 : c0;
        int vv = v0 + t * 8 + vn;
#pragma unroll
        for (int e = 0; e < 2; e++) {
            atomicAdd(&g_gi[(size_t)bq * 3 * HH + vv + e], cr[e]);
            atomicAdd(&g_gi[(size_t)(bq + 8) * 3 * HH + vv + e], cr[2 + e]);
        }
    }
}

// ---------------- K3b: GRU gates (h0 = 0) ----------------
__global__ __launch_bounds__(512) void k_gru_act(const float* __restrict__ b_ih,
                                                 const float* __restrict__ b_hh,
                                                 float* __restrict__ out_hs) {
    const int idx = blockIdx.x * 512 + threadIdx.x;   // 0..16383
    const int b = idx >> 10, j = idx & 1023;
    const float* gi = g_gi + (size_t)b * 3 * HH;
    float r = 1.f / (1.f + expf(-(gi[j] + b_ih[j] + b_hh[j])));
    float z = 1.f / (1.f + expf(-(gi[HH + j] + b_ih[HH + j] + b_hh[HH + j])));
    float n = tanhf(gi[2 * HH + j] + b_ih[2 * HH + j] + r * b_hh[2 * HH + j]);
    float h = (1.f - z) * n;
    g_h[b * HH + j] = h;
    out_hs[b * HH + j] = h;
}

// ---------------- K4: fc_out via HMMA, W loads software-pipelined ----------------
#define HPAD 1048
__global__ __launch_bounds__(256) void k_fc_mma(const float* __restrict__ W,
                                                const float* __restrict__ bias,
                                                float* __restrict__ out) {
    __shared__ __half hsm[16][HPAD];
    const int tid = threadIdx.x, wid = tid >> 5, lane = tid & 31;

    for (int i = tid; i < 8192; i += 256) {
        int r = i >> 9, cc = (i & 511) * 2;
        float2 v = *(const float2*)(g_h + r * HH + cc);
        *(__half2*)&hsm[r][cc] = __floats2half2_rn(v.x, v.y);
    }
    __syncthreads();

    const int v0 = blockIdx.x * 128 + wid * 16;
    int vr0 = v0 + (lane >> 2);       if (vr0 > VV - 1) vr0 = VV - 1;
    int vr1 = v0 + 8 + (lane >> 2);   if (vr1 > VV - 1) vr1 = VV - 1;
    const float* wp0 = W + (size_t)vr0 * HH + 2 * (lane & 3);
    const float* wp1 = W + (size_t)vr1 * HH + 2 * (lane & 3);

    const uint32_t abase = smem_u32(&hsm[0][0])
                         + (uint32_t)((lane & 15) * (HPAD * 2) + (lane >> 4) * 16);

    float c0[4] = {0.f, 0.f, 0.f, 0.f};
    float c1[4] = {0.f, 0.f, 0.f, 0.f};

    float2 wb[2][4];
    wb[0][0] = *(const float2*)(wp0);
    wb[0][1] = *(const float2*)(wp0 + 8);
    wb[0][2] = *(const float2*)(wp1);
    wb[0][3] = *(const float2*)(wp1 + 8);

#pragma unroll 4
    for (int ks = 0; ks < 64; ks++) {
        const int cb = ks & 1, nb = cb ^ 1;
        if (ks < 63) {
            const int kn = (ks + 1) * 16;
            wb[nb][0] = *(const float2*)(wp0 + kn);
            wb[nb][1] = *(const float2*)(wp0 + kn + 8);
            wb[nb][2] = *(const float2*)(wp1 + kn);
            wb[nb][3] = *(const float2*)(wp1 + kn + 8);
        }
        uint32_t a0, a1, a2, a3;
        LDSM4(a0, a1, a2, a3, abase + (uint32_t)(ks * 32));
        uint32_t r00, r01, r10, r11;
        {
            __half2 t0 = __floats2half2_rn(wb[cb][0].x, wb[cb][0].y);
            __half2 t1 = __floats2half2_rn(wb[cb][1].x, wb[cb][1].y);
            __half2 t2 = __floats2half2_rn(wb[cb][2].x, wb[cb][2].y);
            __half2 t3 = __floats2half2_rn(wb[cb][3].x, wb[cb][3].y);
            r00 = *(uint32_t*)&t0; r01 = *(uint32_t*)&t1;
            r10 = *(uint32_t*)&t2; r11 = *(uint32_t*)&t3;
        }
        MMA16816(c0, a0, a1, a2, a3, r00, r01);
        MMA16816(c1, a0, a1, a2, a3, r10, r11);
    }

    const int bq = lane >> 2, vn = 2 * (lane & 3);
#pragma unroll
    for (int t = 0; t < 2; t++) {
        const float* cr = t ? c1 : c0;
        int vv = v0 + t * 8 + vn;
#pragma unroll
        for (int e = 0; e < 2; e++) {
            if (vv + e < VV) {
                float bv = bias[vv + e];
                out[(size_t)bq * VV + vv + e] = cr[e] + bv;
                out[(size_t)(bq + 8) * VV + vv + e] = cr[2 + e] + bv;
            }
        }
    }
}

// ---------------- launch ----------------
extern "C" void kernel_launch(void* const* d_in, const int* in_sizes, int n_in,
                              void* d_out, int out_size) {
    const int*   x      = (const int*)d_in[0];
    const float* dec_hs = (const float*)d_in[1];
    const float* enc    = (const float*)d_in[2];
    const float* emb    = (const float*)d_in[3];
    const float* w1_W   = (const float*)d_in[4];
    const float* w1_b   = (const float*)d_in[5];
    const float* w2_W   = (const float*)d_in[6];
    const float* w2_b   = (const float*)d_in[7];
    const float* va_W   = (const float*)d_in[8];
    // d_in[9] = va_b : softmax shift-invariant, unused
    const float* W_ih   = (const float*)d_in[10];
    // d_in[11] = W_hh : unused, h0 == 0
    const float* b_ih   = (const float*)d_in[12];
    const float* b_hh   = (const float*)d_in[13];
    const float* out_W  = (const float*)d_in[14];
    const float* out_b  = (const float*)d_in[15];

    float* out  = (float*)d_out;
    float* fc   = out;                       // (16, 50257)
    float* hs   = out + BB * VV;             // (1, 16, 1024)
    float* attn = out + BB * VV + BB * HH;   // (16, 512, 1)

    __half *ehi, *whi;
    cudaGetSymbolAddress((void**)&ehi, g_enc_hi);
    cudaGetSymbolAddress((void**)&whi, g_w2_hi);

    static int smem_set = 0;
    if (!smem_set) {
        cudaFuncSetAttribute(k_gemm_score, cudaFuncAttributeMaxDynamicSharedMemorySize, GSMEM);
        smem_set = 1;
    }

    const int encN4 = (SS * BB * HH) / 4;
    const int w2N4  = (HH * HH) / 4;
    k_prep<<<CVT_BLKS + 512, 256>>>(enc, w2_W, ehi, whi,
                                    dec_hs, w1_W, w1_b, encN4, w2N4);          // 0
    k_gemm_score<<<dim3(8, 64), 512, GSMEM>>>(w2_b, va_W);                     // 1
    k_smax_ctx<<<dim3(BB, 9), 512>>>(x, emb, attn);                            // 2
    k_gin_mma<<<dim3(24, 4), 256>>>(W_ih);                                     // 3 <- profiled
    k_gru_act<<<32, 512>>>(b_ih, b_hh, hs);                                    // 4
    k_fc_mma<<<(VV + 127) / 128, 256>>>(out_W, out_b, fc);                     // 5
}

// round 17
// speedup vs baseline: 1.0339x; 1.0339x over previous
#include <cuda_runtime.h>
#include <cuda_fp16.h>
#include <math.h>
#include <stdint.h>

#define BB 16
#define SS 512
#define HH 1024
#define EE 256
#define VV 50257

// ---------------- device scratch (no allocations allowed) ----------------
__device__ float g_dec_proj[BB * HH];
__device__ float g_score[BB * SS];
__device__ float g_gin[BB * (HH + EE)];
__device__ float g_gi[BB * 3 * HH];         // GRU pre-activations (r|z|n)
__device__ float g_h[BB * HH];
__device__ __half g_enc_hi[SS * BB * HH];   // 16 MB
__device__ __half g_w2_hi[HH * HH];         // 2 MB

__device__ __forceinline__ uint32_t smem_u32(const void* p) {
    uint32_t a;
    asm("{ .reg .u64 t; cvta.to.shared.u64 t, %1; cvt.u32.u64 %0, t; }" : "=r"(a) : "l"(p));
    return a;
}
__device__ __forceinline__ float warp_sum(float v) {
#pragma unroll
    for (int o = 16; o; o >>= 1) v += __shfl_xor_sync(0xffffffffu, v, o);
    return v;
}
__device__ __forceinline__ float warp_max(float v) {
#pragma unroll
    for (int o = 16; o; o >>= 1) v = fmaxf(v, __shfl_xor_sync(0xffffffffu, v, o));
    return v;
}

#define LDSM4(r0, r1, r2, r3, addr) \
    asm volatile("ldmatrix.sync.aligned.m8n8.x4.shared.b16 {%0,%1,%2,%3}, [%4];" \
                 : "=r"(r0), "=r"(r1), "=r"(r2), "=r"(r3) : "r"(addr))

#define MMA16816(cc, a0, a1, a2, a3, b0, b1) \
    asm volatile("mma.sync.aligned.m16n8k16.row.col.f32.f16.f16.f32 " \
                 "{%0,%1,%2,%3}, {%4,%5,%6,%7}, {%8,%9}, {%0,%1,%2,%3};" \
                 : "+f"((cc)[0]), "+f"((cc)[1]), "+f"((cc)[2]), "+f"((cc)[3]) \
                 : "r"(a0), "r"(a1), "r"(a2), "r"(a3), "r"(b0), "r"(b1))

#define CP16(dst, src) \
    asm volatile("cp.async.cg.shared.global [%0], [%1], 16;" :: "r"(dst), "l"(src))

// ---------------- K0: fused prep — cvt (0..1183) + dec_proj/zeroing (1184..1695) ----------------
#define CVT_BLKS 1184
__global__ __launch_bounds__(256) void k_prep(const float* __restrict__ enc,
                                              const float* __restrict__ w2,
                                              __half* __restrict__ ehi,
                                              __half* __restrict__ whi,
                                              const float* __restrict__ dec_hs,
                                              const float* __restrict__ w1_W,
                                              const float* __restrict__ w1_b,
                                              int n4e, int n4w) {
    if (blockIdx.x < CVT_BLKS) {
        const int stride = CVT_BLKS * 256;
        const int total = n4e + n4w;
        for (int i = blockIdx.x * 256 + threadIdx.x; i < total; i += stride) {
            if (i < n4e) {
                float4 v = ((const float4*)enc)[i];
                __half2* hp = (__half2*)ehi;
                hp[i * 2]     = __half2(__float2half_rn(v.x), __float2half_rn(v.y));
                hp[i * 2 + 1] = __half2(__float2half_rn(v.z), __float2half_rn(v.w));
            } else {
                int j = i - n4e;
                float4 v = ((const float4*)w2)[j];
                __half2* hp = (__half2*)whi;
                hp[j * 2]     = __half2(__float2half_rn(v.x), __float2half_rn(v.y));
                hp[j * 2 + 1] = __half2(__float2half_rn(v.z), __float2half_rn(v.w));
            }
        }
        return;
    }
    const int blk = blockIdx.x - CVT_BLKS;   // 0..511
    if (threadIdx.x < 16) g_score[blk * 16 + threadIdx.x] = 0.f;
    if (threadIdx.x >= 32 && threadIdx.x < 72)                 // 512*40 = BB*(HH+EE)
        g_gin[blk * 40 + (threadIdx.x - 32)] = 0.f;
    if (threadIdx.x >= 72 && threadIdx.x < 168)                // 512*96 = BB*3*HH
        g_gi[blk * 96 + (threadIdx.x - 72)] = 0.f;

    const int gw = blk * 8 + (threadIdx.x >> 5);   // 0..4095
    const int lane = threadIdx.x & 31;
    const int j = gw >> 2, b0 = (gw & 3) * 4;
    float acc[4] = {0.f, 0.f, 0.f, 0.f};
#pragma unroll
    for (int it = 0; it < 8; it++) {
        const int k = it * 128 + lane * 4;
        float4 w4 = *(const float4*)(w1_W + (size_t)j * HH + k);
#pragma unroll
        for (int b = 0; b < 4; b++) {
            float4 a4 = *(const float4*)(dec_hs + (b0 + b) * HH + k);
            acc[b] += w4.x * a4.x + w4.y * a4.y + w4.z * a4.z + w4.w * a4.w;
        }
    }
#pragma unroll
    for (int b = 0; b < 4; b++) {
        float s = warp_sum(acc[b]);
        if (lane == 0) g_dec_proj[(b0 + b) * HH + j] = s + w1_b[j];
    }
}

// ---------------- K1: fp16 HMMA GEMM + fused score epilogue (R15, unchanged) ----------------
#define MA_A  0u
#define MA_B  10240u
#define STG   20480u
#define GSMEM (4 * 20480)

__global__ void __launch_bounds__(512, 2) k_gemm_score(const float* __restrict__ w2_b,
                                                       const float* __restrict__ va_W) {
    extern __shared__ char dynsmem[];
    const uint32_t sb = smem_u32(dynsmem);

    const int tid = threadIdx.x, wid = tid >> 5, lane = tid & 31;
    const int m0 = blockIdx.y * 128, n0 = blockIdx.x * 128;
    const int wm = wid >> 2, wn = wid & 3;   // warp grid 4M x 4N

    float c[2][4][4];
#pragma unroll
    for (int i = 0; i < 2; i++)
#pragma unroll
        for (int j = 0; j < 4; j++)
#pragma unroll
            for (int e = 0; e < 4; e++) c[i][j][e] = 0.f;

    const int srow = tid >> 2, sq = tid & 3;
    const size_t gA = (size_t)(m0 + srow) * HH + sq * 8;
    const size_t gB = (size_t)(n0 + srow) * HH + sq * 8;
    const uint32_t drow = (uint32_t)(srow * 80 + sq * 16);

#define PREFETCH(st, k0) do {                                               \
        uint32_t db = sb + (uint32_t)(st) * STG + drow;                     \
        CP16(db + MA_A, g_enc_hi + gA + (k0));                              \
        CP16(db + MA_B, g_w2_hi + gB + (k0));                               \
        asm volatile("cp.async.commit_group;" ::: "memory");                \
    } while (0)

    PREFETCH(0, 0);
    PREFETCH(1, 32);
    PREFETCH(2, 64);

    for (int ch = 0; ch < 32; ch++) {
        if (ch <= 29)      asm volatile("cp.async.wait_group 2;" ::: "memory");
        else if (ch == 30) asm volatile("cp.async.wait_group 1;" ::: "memory");
        else               asm volatile("cp.async.wait_group 0;" ::: "memory");
        __syncthreads();
        if (ch + 3 < 32) PREFETCH((ch + 3) & 3, (ch + 3) * 32);

        const uint32_t base = sb + (uint32_t)(ch & 3) * STG;
        const uint32_t aS = base + MA_A, bS = base + MA_B;

#pragma unroll
        for (int kk = 0; kk < 2; kk++) {
            const int lcol = kk * 16 + (lane >> 4) * 8;
            uint32_t am[2][4];
#pragma unroll
            for (int mi = 0; mi < 2; mi++) {
                int m = wm * 32 + mi * 16 + (lane & 15);
                uint32_t off = (uint32_t)(m * 80 + lcol * 2);
                LDSM4(am[mi][0], am[mi][1], am[mi][2], am[mi][3], aS + off);
            }
            uint32_t bhf[4][2];
#pragma unroll
            for (int g = 0; g < 2; g++) {
                int n = wn * 32 + g * 16 + (lane & 15);
                uint32_t off = (uint32_t)(n * 80 + lcol * 2);
                uint32_t r0, r1, r2, r3;
                LDSM4(r0, r1, r2, r3, bS + off);
                bhf[2 * g][0] = r0; bhf[2 * g + 1][0] = r1;
                bhf[2 * g][1] = r2; bhf[2 * g + 1][1] = r3;
            }
#pragma unroll
            for (int mi = 0; mi < 2; mi++)
#pragma unroll
                for (int ni = 0; ni < 4; ni++)
                    MMA16816(c[mi][ni], am[mi][0], am[mi][1], am[mi][2], am[mi][3],
                             bhf[ni][0], bhf[ni][1]);
        }
    }

    const int lq = lane >> 2, lr = lane & 3;
#pragma unroll
    for (int mi = 0; mi < 2; mi++) {
#pragma unroll
        for (int h = 0; h < 2; h++) {
            int r = m0 + wm * 32 + mi * 16 + lq + 8 * h;   // r = s*16 + b
            int b = r & 15, s = r >> 4;
            const float* dec = g_dec_proj + b * HH;
            float acc = 0.f;
#pragma unroll
            for (int ni = 0; ni < 4; ni++) {
#pragma unroll
                for (int e = 0; e < 2; e++) {
                    int col = n0 + wn * 32 + ni * 8 + 2 * lr + e;
                    float v = c[mi][ni][2 * h + e] + dec[col] + w2_b[col];
                    acc += va_W[col] * tanhf(v);
                }
            }
            acc += __shfl_xor_sync(0xffffffffu, acc, 1);
            acc += __shfl_xor_sync(0xffffffffu, acc, 2);
            if (lr == 0) atomicAdd(&g_score[b * SS + s], acc);
        }
    }
}

// ---------------- K2: fused softmax + context(fp16 enc, s-split) + gin ----------------
__global__ __launch_bounds__(512) void k_smax_ctx(const int* __restrict__ x,
                                                  const float* __restrict__ emb,
                                                  float* __restrict__ attn) {
    __shared__ float a[SS];
    __shared__ float red[16];
    __shared__ float bcast;
    const int b = blockIdx.x, tid = threadIdx.x;

    float s0 = g_score[b * SS + tid];
    float m = warp_max(s0);
    if ((tid & 31) == 0) red[tid >> 5] = m;
    __syncthreads();
    if (tid == 0) {
        float mm = red[0];
#pragma unroll
        for (int i = 1; i < 16; i++) mm = fmaxf(mm, red[i]);
        bcast = mm;
    }
    __syncthreads();
    float e0 = expf(s0 - bcast);
    float ws = warp_sum(e0);
    __syncthreads();
    if ((tid & 31) == 0) red[tid >> 5] = ws;
    __syncthreads();
    if (tid == 0) {
        float sum = 0.f;
#pragma unroll
        for (int i = 0; i < 16; i++) sum += red[i];
        bcast = sum;
    }
    __syncthreads();
    a[tid] = e0 / bcast;
    __syncthreads();

    if (blockIdx.y == 8) {
        attn[b * SS + tid] = a[tid];
        if (tid < EE) g_gin[b * (HH + EE) + HH + tid] = emb[(size_t)x[b] * EE + tid];
        return;
    }

    const int sbase = blockIdx.y * 64;
    const __half2* ep = ((const __half2*)g_enc_hi)
                      + ((size_t)sbase * BB + b) * (HH / 2) + tid;
    float accx = 0.f, accy = 0.f;
#pragma unroll 8
    for (int s = 0; s < 64; s++) {
        float w = a[sbase + s];
        float2 v = __half22float2(ep[(size_t)s * BB * (HH / 2)]);
        accx += w * v.x;
        accy += w * v.y;
    }
    atomicAdd(&g_gin[b * (HH + EE) + 2 * tid],     accx);
    atomicAdd(&g_gin[b * (HH + EE) + 2 * tid + 1], accy);
}

// ---------------- K3: GRU input GEMM via HMMA — gi[16x3072] = gin[16x1280] @ W_ih^T ----------------
// grid (24, 8): x = 128-row tile of 3072, y = K-chunk of 160. 192 CTAs, 5.4 KB smem each.
#define KK   (HH + EE)    // 1280
#define KCH  160          // K-chunk
#define GPAD 168          // padded halves: stride 336B, /16 = 21 ≡ 5 (mod 8) — conflict-free
__global__ __launch_bounds__(256) void k_gin_mma(const float* __restrict__ W_ih) {
    __shared__ __half hsm[16][GPAD];
    const int tid = threadIdx.x, wid = tid >> 5, lane = tid & 31;
    const int kbase = blockIdx.y * KCH;

    // load this CTA's gin K-slice (16 x 160 fp32) -> fp16 smem
    for (int i = tid; i < 16 * (KCH / 2); i += 256) {
        int r = i / (KCH / 2), cc = (i % (KCH / 2)) * 2;
        float2 v = *(const float2*)(g_gin + r * KK + kbase + cc);
        *(__half2*)&hsm[r][cc] = __floats2half2_rn(v.x, v.y);
    }
    __syncthreads();

    const int v0 = blockIdx.x * 128 + wid * 16;       // < 3072 always
    const int vr0 = v0 + (lane >> 2);
    const int vr1 = v0 + 8 + (lane >> 2);
    const float* wp0 = W_ih + (size_t)vr0 * KK + kbase + 2 * (lane & 3);
    const float* wp1 = W_ih + (size_t)vr1 * KK + kbase + 2 * (lane & 3);

    const uint32_t abase = smem_u32(&hsm[0][0])
                         + (uint32_t)((lane & 15) * (GPAD * 2) + (lane >> 4) * 16);

    float c0[4] = {0.f, 0.f, 0.f, 0.f};
    float c1[4] = {0.f, 0.f, 0.f, 0.f};

#pragma unroll
    for (int ks = 0; ks < KCH / 16; ks++) {
        const int k0 = ks * 16;
        uint32_t a0, a1, a2, a3;
        LDSM4(a0, a1, a2, a3, abase + (uint32_t)(k0 * 2));
        float2 x0 = *(const float2*)(wp0 + k0);
        float2 x1 = *(const float2*)(wp0 + k0 + 8);
        float2 y0 = *(const float2*)(wp1 + k0);
        float2 y1 = *(const float2*)(wp1 + k0 + 8);
        uint32_t r00, r01, r10, r11;
        {
            __half2 t0 = __floats2half2_rn(x0.x, x0.y);
            __half2 t1 = __floats2half2_rn(x1.x, x1.y);
            __half2 t2 = __floats2half2_rn(y0.x, y0.y);
            __half2 t3 = __floats2half2_rn(y1.x, y1.y);
            r00 = *(uint32_t*)&t0; r01 = *(uint32_t*)&t1;
            r10 = *(uint32_t*)&t2; r11 = *(uint32_t*)&t3;
        }
        MMA16816(c0, a0, a1, a2, a3, r00, r01);
        MMA16816(c1, a0, a1, a2, a3, r10, r11);
    }

    const int bq = lane >> 2, vn = 2 * (lane & 3);
#pragma unroll
    for (int t = 0; t < 2; t++) {
        const float* cr = t ? c1 : c0;
        int vv = v0 + t * 8 + vn;
#pragma unroll
        for (int e = 0; e < 2; e++) {
            atomicAdd(&g_gi[(size_t)bq * 3 * HH + vv + e], cr[e]);
            atomicAdd(&g_gi[(size_t)(bq + 8) * 3 * HH + vv + e], cr[2 + e]);
        }
    }
}

// ---------------- K3b: GRU gates (h0 = 0) ----------------
__global__ __launch_bounds__(512) void k_gru_act(const float* __restrict__ b_ih,
                                                 const float* __restrict__ b_hh,
                                                 float* __restrict__ out_hs) {
    const int idx = blockIdx.x * 512 + threadIdx.x;   // 0..16383
    const int b = idx >> 10, j = idx & 1023;
    const float* gi = g_gi + (size_t)b * 3 * HH;
    float r = 1.f / (1.f + expf(-(gi[j] + b_ih[j] + b_hh[j])));
    float z = 1.f / (1.f + expf(-(gi[HH + j] + b_ih[HH + j] + b_hh[HH + j])));
    float n = tanhf(gi[2 * HH + j] + b_ih[2 * HH + j] + r * b_hh[2 * HH + j]);
    float h = (1.f - z) * n;
    g_h[b * HH + j] = h;
    out_hs[b * HH + j] = h;
}

// ---------------- K4: fc_out via HMMA, W loads software-pipelined ----------------
#define HPAD 1048
__global__ __launch_bounds__(256) void k_fc_mma(const float* __restrict__ W,
                                                const float* __restrict__ bias,
                                                float* __restrict__ out) {
    __shared__ __half hsm[16][HPAD];
    const int tid = threadIdx.x, wid = tid >> 5, lane = tid & 31;

    for (int i = tid; i < 8192; i += 256) {
        int r = i >> 9, cc = (i & 511) * 2;
        float2 v = *(const float2*)(g_h + r * HH + cc);
        *(__half2*)&hsm[r][cc] = __floats2half2_rn(v.x, v.y);
    }
    __syncthreads();

    const int v0 = blockIdx.x * 128 + wid * 16;
    int vr0 = v0 + (lane >> 2);       if (vr0 > VV - 1) vr0 = VV - 1;
    int vr1 = v0 + 8 + (lane >> 2);   if (vr1 > VV - 1) vr1 = VV - 1;
    const float* wp0 = W + (size_t)vr0 * HH + 2 * (lane & 3);
    const float* wp1 = W + (size_t)vr1 * HH + 2 * (lane & 3);

    const uint32_t abase = smem_u32(&hsm[0][0])
                         + (uint32_t)((lane & 15) * (HPAD * 2) + (lane >> 4) * 16);

    float c0[4] = {0.f, 0.f, 0.f, 0.f};
    float c1[4] = {0.f, 0.f, 0.f, 0.f};

    float2 wb[2][4];
    wb[0][0] = *(const float2*)(wp0);
    wb[0][1] = *(const float2*)(wp0 + 8);
    wb[0][2] = *(const float2*)(wp1);
    wb[0][3] = *(const float2*)(wp1 + 8);

#pragma unroll 4
    for (int ks = 0; ks < 64; ks++) {
        const int cb = ks & 1, nb = cb ^ 1;
        if (ks < 63) {
            const int kn = (ks + 1) * 16;
            wb[nb][0] = *(const float2*)(wp0 + kn);
            wb[nb][1] = *(const float2*)(wp0 + kn + 8);
            wb[nb][2] = *(const float2*)(wp1 + kn);
            wb[nb][3] = *(const float2*)(wp1 + kn + 8);
        }
        uint32_t a0, a1, a2, a3;
        LDSM4(a0, a1, a2, a3, abase + (uint32_t)(ks * 32));
        uint32_t r00, r01, r10, r11;
        {
            __half2 t0 = __floats2half2_rn(wb[cb][0].x, wb[cb][0].y);
            __half2 t1 = __floats2half2_rn(wb[cb][1].x, wb[cb][1].y);
            __half2 t2 = __floats2half2_rn(wb[cb][2].x, wb[cb][2].y);
            __half2 t3 = __floats2half2_rn(wb[cb][3].x, wb[cb][3].y);
            r00 = *(uint32_t*)&t0; r01 = *(uint32_t*)&t1;
            r10 = *(uint32_t*)&t2; r11 = *(uint32_t*)&t3;
        }
        MMA16816(c0, a0, a1, a2, a3, r00, r01);
        MMA16816(c1, a0, a1, a2, a3, r10, r11);
    }

    const int bq = lane >> 2, vn = 2 * (lane & 3);
#pragma unroll
    for (int t = 0; t < 2; t++) {
        const float* cr = t ? c1 : c0;
        int vv = v0 + t * 8 + vn;
#pragma unroll
        for (int e = 0; e < 2; e++) {
            if (vv + e < VV) {
                float bv = bias[vv + e];
                out[(size_t)bq * VV + vv + e] = cr[e] + bv;
                out[(size_t)(bq + 8) * VV + vv + e] = cr[2 + e] + bv;
            }
        }
    }
}

// ---------------- launch ----------------
extern "C" void kernel_launch(void* const* d_in, const int* in_sizes, int n_in,
                              void* d_out, int out_size) {
    const int*   x      = (const int*)d_in[0];
    const float* dec_hs = (const float*)d_in[1];
    const float* enc    = (const float*)d_in[2];
    const float* emb    = (const float*)d_in[3];
    const float* w1_W   = (const float*)d_in[4];
    const float* w1_b   = (const float*)d_in[5];
    const float* w2_W   = (const float*)d_in[6];
    const float* w2_b   = (const float*)d_in[7];
    const float* va_W   = (const float*)d_in[8];
    // d_in[9] = va_b : softmax shift-invariant, unused
    const float* W_ih   = (const float*)d_in[10];
    // d_in[11] = W_hh : unused, h0 == 0
    const float* b_ih   = (const float*)d_in[12];
    const float* b_hh   = (const float*)d_in[13];
    const float* out_W  = (const float*)d_in[14];
    const float* out_b  = (const float*)d_in[15];

    float* out  = (float*)d_out;
    float* fc   = out;                       // (16, 50257)
    float* hs   = out + BB * VV;             // (1, 16, 1024)
    float* attn = out + BB * VV + BB * HH;   // (16, 512, 1)

    __half *ehi, *whi;
    cudaGetSymbolAddress((void**)&ehi, g_enc_hi);
    cudaGetSymbolAddress((void**)&whi, g_w2_hi);

    static int smem_set = 0;
    if (!smem_set) {
        cudaFuncSetAttribute(k_gemm_score, cudaFuncAttributeMaxDynamicSharedMemorySize, GSMEM);
        smem_set = 1;
    }

    const int encN4 = (SS * BB * HH) / 4;
    const int w2N4  = (HH * HH) / 4;
    k_prep<<<CVT_BLKS + 512, 256>>>(enc, w2_W, ehi, whi,
                                    dec_hs, w1_W, w1_b, encN4, w2N4);          // 0
    k_gemm_score<<<dim3(8, 64), 512, GSMEM>>>(w2_b, va_W);                     // 1
    k_smax_ctx<<<dim3(BB, 9), 512>>>(x, emb, attn);                            // 2
    k_gin_mma<<<dim3(24, 8), 256>>>(W_ih);                                     // 3 <- profiled
    k_gru_act<<<32, 512>>>(b_ih, b_hh, hs);                                    // 4
    k_fc_mma<<<(VV + 127) / 128, 256>>>(out_W, out_b, fc);                     // 5
}